// round 9
// baseline (speedup 1.0000x reference)
#include <cuda_runtime.h>

#define MAXN 50176
#define MAXE 850176
#define GRID 888              // 148 SMs x 6 blocks: co-resident on B300(148)/GB300(152)
#define CTA  256
#define NWARP 8

// -------- scratch (device globals; zero at load; each replay self-restores) --------
__device__ float  g_xl[MAXN * 64];
__device__ float  g_si[MAXN];
__device__ float  g_sj[MAXN];
__device__ int    g_deg[MAXN];          // reset in P3
__device__ int    g_rowptr[MAXN + 1];
__device__ int    g_rank[MAXE];
__device__ float2 g_epack[MAXE];        // (.x = src bits, .y = weight)
__device__ float  g_bnsum[128];         // reset by block 0 at end
__device__ int    g_bpart[GRID];
__device__ unsigned long long g_bar;    // monotonic ticket counter (never reset)

struct ScanS { int vals[128]; int wred[NWARP]; int off; };
union SmemU {
    float2 Wt2[64][32];                 // 16 KB (P0 gemm)
    ScanS  scan;                        // P1/P2
    float  sred[128];                   // P4 BN partials
    float  bnss[128];                   // P5 scale[0:64) shift[64:128)
};

// Grid-wide barrier: monotonic ticket scheme (increments grouped per phase).
__device__ __forceinline__ void grid_barrier() {
    __syncthreads();
    if (threadIdx.x == 0) {
        __threadfence();
        unsigned long long t = atomicAdd(&g_bar, 1ULL);
        unsigned long long target = t - (t % GRID) + GRID;
        while (*(volatile unsigned long long*)&g_bar < target) __nanosleep(64);
    }
    __syncthreads();
}

__device__ __forceinline__ void scat_one(int s, int d, int pos) {
    float a = g_si[d] + g_sj[s];
    a = a >= 0.f ? a : 0.2f * a;
    g_epack[pos] = make_float2(__int_as_float(s), __expf(a));
}

__global__ void __launch_bounds__(CTA, 6) k_fused(
    const float* __restrict__ x, const int* __restrict__ ei,
    const float* __restrict__ emb, const float* __restrict__ W,
    const float* __restrict__ att_i, const float* __restrict__ att_j,
    const float* __restrict__ att_em_i, const float* __restrict__ att_em_j,
    const float* __restrict__ bias, const float* __restrict__ gamma,
    const float* __restrict__ beta, float* __restrict__ out,
    int N, int E)
{
    __shared__ SmemU sm;
    const int tid = threadIdx.x, bid = blockIdx.x;
    const int lane = tid & 31, wid = tid >> 5;
    const int gtid = bid * CTA + tid;
    const int GT = GRID * CTA;
    const int E4 = E >> 2;

    // ================= P0: count(+rank)  ||  gemm + logits =================
    for (int s = tid; s < 2048; s += CTA) {
        int k = s >> 5, l = s & 31;
        sm.Wt2[k][l] = make_float2(W[(2 * l) * 64 + k], W[(2 * l + 1) * 64 + k]);
    }
    __syncthreads();

    for (int t = gtid; t < E4; t += GT) {
        int4 d4 = *(const int4*)&ei[E + 4 * t];
        int4 r4;
        r4.x = atomicAdd(&g_deg[d4.x], 1);
        r4.y = atomicAdd(&g_deg[d4.y], 1);
        r4.z = atomicAdd(&g_deg[d4.z], 1);
        r4.w = atomicAdd(&g_deg[d4.w], 1);
        *(int4*)&g_rank[4 * t] = r4;
    }
    for (int e = 4 * E4 + gtid; e < E; e += GT)
        g_rank[e] = atomicAdd(&g_deg[ei[E + e]], 1);

    {
        int c0 = 2 * lane;
        float ai0 = att_i[c0],    ai1 = att_i[c0 + 1];
        float aj0 = att_j[c0],    aj1 = att_j[c0 + 1];
        float e0i = att_em_i[c0], e1i = att_em_i[c0 + 1];
        float e0j = att_em_j[c0], e1j = att_em_j[c0 + 1];
        for (int r = bid * NWARP + wid; r < N; r += GRID * NWARP) {
            float xv0 = x[r * 64 + lane];
            float xv1 = x[r * 64 + 32 + lane];
            float a0 = 0.f, a1 = 0.f;
#pragma unroll
            for (int k = 0; k < 32; k++) {
                float xk = __shfl_sync(0xffffffffu, xv0, k);
                float2 w = sm.Wt2[k][lane];
                a0 = fmaf(xk, w.x, a0);
                a1 = fmaf(xk, w.y, a1);
            }
#pragma unroll
            for (int k = 0; k < 32; k++) {
                float xk = __shfl_sync(0xffffffffu, xv1, k);
                float2 w = sm.Wt2[32 + k][lane];
                a0 = fmaf(xk, w.x, a0);
                a1 = fmaf(xk, w.y, a1);
            }
            *(float2*)&g_xl[r * 64 + c0] = make_float2(a0, a1);

            float2 em = *(const float2*)&emb[r * 64 + c0];
            float si = a0 * ai0 + a1 * ai1 + em.x * e0i + em.y * e1i;
            float sj = a0 * aj0 + a1 * aj1 + em.x * e0j + em.y * e1j;
#pragma unroll
            for (int o = 16; o; o >>= 1) {
                si += __shfl_xor_sync(0xffffffffu, si, o);
                sj += __shfl_xor_sync(0xffffffffu, sj, o);
            }
            if (lane == 0) { g_si[r] = si; g_sj[r] = sj; }
        }
    }
    grid_barrier();

    // ================= P1: per-block partial sums of deg ===================
    const int CH = (N + GRID - 1) / GRID;        // 57 for N=50000 (<=128 required)
    int beg = bid * CH;
    int cnt = N - beg; if (cnt < 0) cnt = 0; if (cnt > CH) cnt = CH;
    {
        int v = (tid < cnt) ? g_deg[beg + tid] : 0;
#pragma unroll
        for (int o = 16; o; o >>= 1) v += __shfl_xor_sync(0xffffffffu, v, o);
        if (lane == 0) sm.scan.wred[wid] = v;
        __syncthreads();
        if (tid == 0) {
            int s = 0;
#pragma unroll
            for (int w2 = 0; w2 < NWARP; w2++) s += sm.scan.wred[w2];
            g_bpart[bid] = s;
        }
    }
    grid_barrier();

    // ================= P2: block prefix + local scan -> rowptr =============
    {
        int part = 0;
        for (int j = tid; j < bid; j += CTA) part += g_bpart[j];
#pragma unroll
        for (int o = 16; o; o >>= 1) part += __shfl_xor_sync(0xffffffffu, part, o);
        if (lane == 0) sm.scan.wred[wid] = part;
        __syncthreads();
        if (tid == 0) {
            int s = 0;
#pragma unroll
            for (int w2 = 0; w2 < NWARP; w2++) s += sm.scan.wred[w2];
            sm.scan.off = s;
            if (bid == GRID - 1) g_rowptr[N] = s + g_bpart[bid];
        }
        if (tid < 128) sm.scan.vals[tid] = 0;
        __syncthreads();
        int myv = 0;
        if (tid < cnt) { myv = g_deg[beg + tid]; sm.scan.vals[tid] = myv; }
        __syncthreads();
#pragma unroll
        for (int d = 1; d < 128; d <<= 1) {
            int add = (tid < 128 && tid >= d) ? sm.scan.vals[tid - d] : 0;
            __syncthreads();
            if (tid < 128) sm.scan.vals[tid] += add;
            __syncthreads();
        }
        if (tid < cnt)
            g_rowptr[beg + tid] = sm.scan.off + sm.scan.vals[tid] - myv;
    }
    grid_barrier();

    // ================= P3: edge scatter (no atomics) + deg reset ===========
    for (int t = gtid; t < E4; t += GT) {
        int4 s4 = *(const int4*)&ei[4 * t];
        int4 d4 = *(const int4*)&ei[E + 4 * t];
        int4 r4 = *(const int4*)&g_rank[4 * t];
        scat_one(s4.x, d4.x, g_rowptr[d4.x] + r4.x);
        scat_one(s4.y, d4.y, g_rowptr[d4.y] + r4.y);
        scat_one(s4.z, d4.z, g_rowptr[d4.z] + r4.z);
        scat_one(s4.w, d4.w, g_rowptr[d4.w] + r4.w);
    }
    for (int e = 4 * E4 + gtid; e < E; e += GT) {
        int s = ei[e], d = ei[E + e];
        scat_one(s, d, g_rowptr[d] + g_rank[e]);
    }
    for (int i = gtid; i < N; i += GT) g_deg[i] = 0;    // restore for next replay
    grid_barrier();

    // ===== P4: weighted gather (self-loop analytic, denom inline) + BN stats =====
    if (tid < 128) sm.sred[tid] = 0.f;
    __syncthreads();
    {
        int c0 = 2 * lane;
        float2 b2 = *(const float2*)&bias[c0];
        float p0 = 0.f, p1 = 0.f, q0 = 0.f, q1 = 0.f;

        for (int i = bid * NWARP + wid; i < N; i += GRID * NWARP) {
            int kb = g_rowptr[i], ke = g_rowptr[i + 1];
            // self loop: computed analytically, contiguous xl load
            float as = g_si[i] + g_sj[i];
            as = as >= 0.f ? as : 0.2f * as;
            float ws = __expf(as);
            float2 vs = *(const float2*)&g_xl[i * 64 + c0];
            float ssum = ws;
            float ax = ws * vs.x, ay = ws * vs.y;

            int k = kb;
            for (; k + 4 <= ke; k += 4) {
                float2 e0 = g_epack[k],     e1 = g_epack[k + 1];
                float2 e2 = g_epack[k + 2], e3 = g_epack[k + 3];
                int s0 = __float_as_int(e0.x), s1 = __float_as_int(e1.x);
                int s2 = __float_as_int(e2.x), s3 = __float_as_int(e3.x);
                float2 v0 = *(const float2*)&g_xl[s0 * 64 + c0];
                float2 v1 = *(const float2*)&g_xl[s1 * 64 + c0];
                float2 v2 = *(const float2*)&g_xl[s2 * 64 + c0];
                float2 v3 = *(const float2*)&g_xl[s3 * 64 + c0];
                ssum += (e0.y + e1.y) + (e2.y + e3.y);
                ax = fmaf(e0.y, v0.x, ax); ay = fmaf(e0.y, v0.y, ay);
                ax = fmaf(e1.y, v1.x, ax); ay = fmaf(e1.y, v1.y, ay);
                ax = fmaf(e2.y, v2.x, ax); ay = fmaf(e2.y, v2.y, ay);
                ax = fmaf(e3.y, v3.x, ax); ay = fmaf(e3.y, v3.y, ay);
            }
            for (; k < ke; ++k) {
                float2 e = g_epack[k];
                int s = __float_as_int(e.x);
                float2 v = *(const float2*)&g_xl[s * 64 + c0];
                ssum += e.y;
                ax = fmaf(e.y, v.x, ax);
                ay = fmaf(e.y, v.y, ay);
            }
            float inv = 1.f / (ssum + 1e-16f);
            float ox = fmaf(ax, inv, b2.x);
            float oy = fmaf(ay, inv, b2.y);
            *(float2*)&out[i * 64 + c0] = make_float2(ox, oy);
            p0 += ox; q0 = fmaf(ox, ox, q0);
            p1 += oy; q1 = fmaf(oy, oy, q1);
        }
        atomicAdd(&sm.sred[c0],          p0);
        atomicAdd(&sm.sred[c0 + 1],      p1);
        atomicAdd(&sm.sred[64 + c0],     q0);
        atomicAdd(&sm.sred[64 + c0 + 1], q1);
    }
    __syncthreads();
    if (tid < 128) atomicAdd(&g_bnsum[tid], sm.sred[tid]);
    grid_barrier();

    // ================= P5: BN apply + ReLU =================================
    if (tid < 64) {
        double mu  = (double)g_bnsum[tid] / (double)N;
        double var = (double)g_bnsum[64 + tid] / (double)N - mu * mu;
        float sc = (float)rsqrt(var + 1e-5) * gamma[tid];
        sm.bnss[tid]      = sc;
        sm.bnss[64 + tid] = fmaf(-(float)mu, sc, beta[tid]);
    }
    __syncthreads();
    {
        int NV = N * 16;                           // float4 elements
        for (int v = gtid; v < NV; v += GT) {
            float4 o4 = *(float4*)(out + v * 4);
            int c0 = (v & 15) * 4;
            o4.x = fmaxf(fmaf(o4.x, sm.bnss[c0],     sm.bnss[64 + c0]),     0.f);
            o4.y = fmaxf(fmaf(o4.y, sm.bnss[c0 + 1], sm.bnss[64 + c0 + 1]), 0.f);
            o4.z = fmaxf(fmaf(o4.z, sm.bnss[c0 + 2], sm.bnss[64 + c0 + 2]), 0.f);
            o4.w = fmaxf(fmaf(o4.w, sm.bnss[c0 + 3], sm.bnss[64 + c0 + 3]), 0.f);
            *(float4*)(out + v * 4) = o4;
        }
    }

    // final barrier: arrive-all; block 0 waits then resets g_bnsum
    __syncthreads();
    if (tid == 0) {
        __threadfence();
        unsigned long long t = atomicAdd(&g_bar, 1ULL);
        if (bid == 0) {
            unsigned long long target = t - (t % GRID) + GRID;
            while (*(volatile unsigned long long*)&g_bar < target) __nanosleep(64);
        }
    }
    __syncthreads();
    if (bid == 0 && tid < 128) g_bnsum[tid] = 0.f;
}

extern "C" void kernel_launch(void* const* d_in, const int* in_sizes, int n_in,
                              void* d_out, int out_size) {
    const float* x        = (const float*)d_in[0];
    const int*   ei       = (const int*)d_in[1];
    const float* emb      = (const float*)d_in[2];
    const float* W        = (const float*)d_in[3];
    const float* att_i    = (const float*)d_in[4];
    const float* att_j    = (const float*)d_in[5];
    const float* att_em_i = (const float*)d_in[6];
    const float* att_em_j = (const float*)d_in[7];
    const float* bias     = (const float*)d_in[8];
    const float* gamma    = (const float*)d_in[9];
    const float* beta     = (const float*)d_in[10];
    float* out = (float*)d_out;

    int N = in_sizes[0] / 64;
    int E = in_sizes[1] / 2;

    k_fused<<<GRID, CTA>>>(x, ei, emb, W, att_i, att_j, att_em_i, att_em_j,
                           bias, gamma, beta, out, N, E);
}

// round 10
// speedup vs baseline: 1.0229x; 1.0229x over previous
#include <cuda_runtime.h>

#define MAXN 50176
#define MAXE 850176
#define GRID 888              // 148 SMs x 6 blocks: co-resident on B300(148)/GB300(152)
#define GA   444              // A-blocks: count+scan   (bid < GA)
#define GB   (GRID - GA)      // B-blocks: gemm+logits  (bid >= GA)
#define CTA  256
#define NWARP 8

// -------- scratch (device globals; zero at load; each replay self-restores) --------
__device__ float  g_xl[MAXN * 64];
__device__ float  g_si[MAXN];
__device__ float  g_sj[MAXN];
__device__ int    g_deg[MAXN];          // reset in P3
__device__ int    g_rowptr[MAXN + 1];
__device__ int    g_rank[MAXE];
__device__ __align__(16) float2 g_epack[MAXE];  // (.x = src bits, .y = weight)
__device__ float  g_bnsum[128];         // reset by block 0 at end
__device__ int    g_bpart[GA];
__device__ unsigned long long g_bar;    // global ticket counter (monotonic)
__device__ unsigned long long g_barA;   // A-group ticket counter (monotonic)

struct ScanS { int vals[128]; int wred[NWARP]; int off; };
union SmemU {
    float2 Wt2[64][32];                 // 16 KB (B-blocks: gemm)
    ScanS  scan;                        // A-blocks: scan
    float  sred[128];                   // P4 BN partials
    float  bnss[128];                   // P5 scale[0:64) shift[64:128)
};

__device__ __forceinline__ void bar_wait(unsigned long long* ctr, int group) {
    __syncthreads();
    if (threadIdx.x == 0) {
        __threadfence();
        unsigned long long t = atomicAdd(ctr, 1ULL);
        unsigned long long target = t - (t % group) + group;
        while (*(volatile unsigned long long*)ctr < target) __nanosleep(64);
    }
    __syncthreads();
}

__device__ __forceinline__ void scat_one(int s, int d, int pos) {
    float a = g_si[d] + g_sj[s];
    a = a >= 0.f ? a : 0.2f * a;
    g_epack[pos] = make_float2(__int_as_float(s), __expf(a));
}

__global__ void __launch_bounds__(CTA, 6) k_fused(
    const float* __restrict__ x, const int* __restrict__ ei,
    const float* __restrict__ emb, const float* __restrict__ W,
    const float* __restrict__ att_i, const float* __restrict__ att_j,
    const float* __restrict__ att_em_i, const float* __restrict__ att_em_j,
    const float* __restrict__ bias, const float* __restrict__ gamma,
    const float* __restrict__ beta, float* __restrict__ out,
    int N, int E)
{
    __shared__ SmemU sm;
    const int tid = threadIdx.x, bid = blockIdx.x;
    const int lane = tid & 31, wid = tid >> 5;
    const int gtid = bid * CTA + tid;
    const int GT = GRID * CTA;
    const int E4 = E >> 2;

    if (bid < GA) {
        // ============ A: count(+rank) -> scan P1 -> scan P2 ============
        {
            const int AT = GA * CTA;
            int at = bid * CTA + tid;
            for (int t = at; t < E4; t += AT) {
                int4 d4 = *(const int4*)&ei[E + 4 * t];
                int4 r4;
                r4.x = atomicAdd(&g_deg[d4.x], 1);
                r4.y = atomicAdd(&g_deg[d4.y], 1);
                r4.z = atomicAdd(&g_deg[d4.z], 1);
                r4.w = atomicAdd(&g_deg[d4.w], 1);
                *(int4*)&g_rank[4 * t] = r4;
            }
            for (int e = 4 * E4 + at; e < E; e += AT)
                g_rank[e] = atomicAdd(&g_deg[ei[E + e]], 1);
        }
        bar_wait(&g_barA, GA);

        const int CH = (N + GA - 1) / GA;        // 113 for N=50000 (<=128 required)
        int beg = bid * CH;
        int cnt = N - beg; if (cnt < 0) cnt = 0; if (cnt > CH) cnt = CH;
        {   // P1: block partial sum of deg
            int v = (tid < cnt) ? g_deg[beg + tid] : 0;
#pragma unroll
            for (int o = 16; o; o >>= 1) v += __shfl_xor_sync(0xffffffffu, v, o);
            if (lane == 0) sm.scan.wred[wid] = v;
            __syncthreads();
            if (tid == 0) {
                int s = 0;
#pragma unroll
                for (int w2 = 0; w2 < NWARP; w2++) s += sm.scan.wred[w2];
                g_bpart[bid] = s;
            }
        }
        bar_wait(&g_barA, GA);
        {   // P2: block prefix + local scan -> rowptr
            int part = 0;
            for (int j = tid; j < bid; j += CTA) part += g_bpart[j];
#pragma unroll
            for (int o = 16; o; o >>= 1) part += __shfl_xor_sync(0xffffffffu, part, o);
            if (lane == 0) sm.scan.wred[wid] = part;
            __syncthreads();
            if (tid == 0) {
                int s = 0;
#pragma unroll
                for (int w2 = 0; w2 < NWARP; w2++) s += sm.scan.wred[w2];
                sm.scan.off = s;
                if (bid == GA - 1) g_rowptr[N] = s + g_bpart[bid];
            }
            if (tid < 128) sm.scan.vals[tid] = 0;
            __syncthreads();
            int myv = 0;
            if (tid < cnt) { myv = g_deg[beg + tid]; sm.scan.vals[tid] = myv; }
            __syncthreads();
#pragma unroll
            for (int d = 1; d < 128; d <<= 1) {
                int add = (tid < 128 && tid >= d) ? sm.scan.vals[tid - d] : 0;
                __syncthreads();
                if (tid < 128) sm.scan.vals[tid] += add;
                __syncthreads();
            }
            if (tid < cnt)
                g_rowptr[beg + tid] = sm.scan.off + sm.scan.vals[tid] - myv;
        }
    } else {
        // ============ B: gemm + per-node logits (runs concurrently) ============
        for (int s = tid; s < 2048; s += CTA) {
            int k = s >> 5, l = s & 31;
            sm.Wt2[k][l] = make_float2(W[(2 * l) * 64 + k], W[(2 * l + 1) * 64 + k]);
        }
        __syncthreads();
        int c0 = 2 * lane;
        float ai0 = att_i[c0],    ai1 = att_i[c0 + 1];
        float aj0 = att_j[c0],    aj1 = att_j[c0 + 1];
        float e0i = att_em_i[c0], e1i = att_em_i[c0 + 1];
        float e0j = att_em_j[c0], e1j = att_em_j[c0 + 1];
        for (int r = (bid - GA) * NWARP + wid; r < N; r += GB * NWARP) {
            float xv0 = x[r * 64 + lane];
            float xv1 = x[r * 64 + 32 + lane];
            float a0 = 0.f, a1 = 0.f;
#pragma unroll
            for (int k = 0; k < 32; k++) {
                float xk = __shfl_sync(0xffffffffu, xv0, k);
                float2 w = sm.Wt2[k][lane];
                a0 = fmaf(xk, w.x, a0);
                a1 = fmaf(xk, w.y, a1);
            }
#pragma unroll
            for (int k = 0; k < 32; k++) {
                float xk = __shfl_sync(0xffffffffu, xv1, k);
                float2 w = sm.Wt2[32 + k][lane];
                a0 = fmaf(xk, w.x, a0);
                a1 = fmaf(xk, w.y, a1);
            }
            *(float2*)&g_xl[r * 64 + c0] = make_float2(a0, a1);

            float2 em = *(const float2*)&emb[r * 64 + c0];
            float si = a0 * ai0 + a1 * ai1 + em.x * e0i + em.y * e1i;
            float sj = a0 * aj0 + a1 * aj1 + em.x * e0j + em.y * e1j;
#pragma unroll
            for (int o = 16; o; o >>= 1) {
                si += __shfl_xor_sync(0xffffffffu, si, o);
                sj += __shfl_xor_sync(0xffffffffu, sj, o);
            }
            if (lane == 0) { g_si[r] = si; g_sj[r] = sj; }
        }
    }
    bar_wait(&g_bar, GRID);          // rowptr, rank, xl, si, sj all ready

    // ================= P3: edge scatter (no atomics) + deg reset ===========
    for (int t = gtid; t < E4; t += GT) {
        int4 s4 = *(const int4*)&ei[4 * t];
        int4 d4 = *(const int4*)&ei[E + 4 * t];
        int4 r4 = *(const int4*)&g_rank[4 * t];
        scat_one(s4.x, d4.x, g_rowptr[d4.x] + r4.x);
        scat_one(s4.y, d4.y, g_rowptr[d4.y] + r4.y);
        scat_one(s4.z, d4.z, g_rowptr[d4.z] + r4.z);
        scat_one(s4.w, d4.w, g_rowptr[d4.w] + r4.w);
    }
    for (int e = 4 * E4 + gtid; e < E; e += GT) {
        int s = ei[e], d = ei[E + e];
        scat_one(s, d, g_rowptr[d] + g_rank[e]);
    }
    for (int i = gtid; i < N; i += GT) g_deg[i] = 0;    // restore for next replay
    bar_wait(&g_bar, GRID);

    // ===== P4: weighted gather (self-loop analytic, denom inline) + BN stats =====
    if (tid < 128) sm.sred[tid] = 0.f;
    __syncthreads();
    {
        int c0 = 2 * lane;
        float2 b2 = *(const float2*)&bias[c0];
        float p0 = 0.f, p1 = 0.f, q0 = 0.f, q1 = 0.f;

        for (int i = bid * NWARP + wid; i < N; i += GRID * NWARP) {
            int kb = g_rowptr[i], ke = g_rowptr[i + 1];
            float as = g_si[i] + g_sj[i];            // self loop, analytic
            as = as >= 0.f ? as : 0.2f * as;
            float ws = __expf(as);
            float2 vs = *(const float2*)&g_xl[i * 64 + c0];
            float ssum = ws;
            float ax = ws * vs.x, ay = ws * vs.y;

            int k = kb;
            if ((k & 1) && k < ke) {                 // peel to 16B alignment
                float2 e = g_epack[k];
                int s = __float_as_int(e.x);
                float2 v = *(const float2*)&g_xl[s * 64 + c0];
                ssum += e.y;
                ax = fmaf(e.y, v.x, ax);
                ay = fmaf(e.y, v.y, ay);
                ++k;
            }
            for (; k + 4 <= ke; k += 4) {            // 2x float4 = 4 packed edges
                float4 ea = *(const float4*)&g_epack[k];
                float4 eb = *(const float4*)&g_epack[k + 2];
                int s0 = __float_as_int(ea.x), s1 = __float_as_int(ea.z);
                int s2 = __float_as_int(eb.x), s3 = __float_as_int(eb.z);
                float2 v0 = *(const float2*)&g_xl[s0 * 64 + c0];
                float2 v1 = *(const float2*)&g_xl[s1 * 64 + c0];
                float2 v2 = *(const float2*)&g_xl[s2 * 64 + c0];
                float2 v3 = *(const float2*)&g_xl[s3 * 64 + c0];
                ssum += (ea.y + ea.w) + (eb.y + eb.w);
                ax = fmaf(ea.y, v0.x, ax); ay = fmaf(ea.y, v0.y, ay);
                ax = fmaf(ea.w, v1.x, ax); ay = fmaf(ea.w, v1.y, ay);
                ax = fmaf(eb.y, v2.x, ax); ay = fmaf(eb.y, v2.y, ay);
                ax = fmaf(eb.w, v3.x, ax); ay = fmaf(eb.w, v3.y, ay);
            }
            for (; k < ke; ++k) {
                float2 e = g_epack[k];
                int s = __float_as_int(e.x);
                float2 v = *(const float2*)&g_xl[s * 64 + c0];
                ssum += e.y;
                ax = fmaf(e.y, v.x, ax);
                ay = fmaf(e.y, v.y, ay);
            }
            float inv = 1.f / (ssum + 1e-16f);
            float ox = fmaf(ax, inv, b2.x);
            float oy = fmaf(ay, inv, b2.y);
            *(float2*)&out[i * 64 + c0] = make_float2(ox, oy);
            p0 += ox; q0 = fmaf(ox, ox, q0);
            p1 += oy; q1 = fmaf(oy, oy, q1);
        }
        atomicAdd(&sm.sred[c0],          p0);
        atomicAdd(&sm.sred[c0 + 1],      p1);
        atomicAdd(&sm.sred[64 + c0],     q0);
        atomicAdd(&sm.sred[64 + c0 + 1], q1);
    }
    __syncthreads();
    if (tid < 128) atomicAdd(&g_bnsum[tid], sm.sred[tid]);
    bar_wait(&g_bar, GRID);

    // ================= P5: BN apply + ReLU =================================
    if (tid < 64) {
        double mu  = (double)g_bnsum[tid] / (double)N;
        double var = (double)g_bnsum[64 + tid] / (double)N - mu * mu;
        float sc = (float)rsqrt(var + 1e-5) * gamma[tid];
        sm.bnss[tid]      = sc;
        sm.bnss[64 + tid] = fmaf(-(float)mu, sc, beta[tid]);
    }
    __syncthreads();
    {
        int NV = N * 16;                             // float4 elements
        for (int v = gtid; v < NV; v += GT) {
            float4 o4 = *(float4*)(out + v * 4);
            int c0 = (v & 15) * 4;
            o4.x = fmaxf(fmaf(o4.x, sm.bnss[c0],     sm.bnss[64 + c0]),     0.f);
            o4.y = fmaxf(fmaf(o4.y, sm.bnss[c0 + 1], sm.bnss[64 + c0 + 1]), 0.f);
            o4.z = fmaxf(fmaf(o4.z, sm.bnss[c0 + 2], sm.bnss[64 + c0 + 2]), 0.f);
            o4.w = fmaxf(fmaf(o4.w, sm.bnss[c0 + 3], sm.bnss[64 + c0 + 3]), 0.f);
            *(float4*)(out + v * 4) = o4;
        }
    }

    // final barrier: arrive-all; block 0 waits then resets g_bnsum
    __syncthreads();
    if (tid == 0) {
        __threadfence();
        unsigned long long t = atomicAdd(&g_bar, 1ULL);
        if (bid == 0) {
            unsigned long long target = t - (t % GRID) + GRID;
            while (*(volatile unsigned long long*)&g_bar < target) __nanosleep(64);
        }
    }
    __syncthreads();
    if (bid == 0 && tid < 128) g_bnsum[tid] = 0.f;
}

extern "C" void kernel_launch(void* const* d_in, const int* in_sizes, int n_in,
                              void* d_out, int out_size) {
    const float* x        = (const float*)d_in[0];
    const int*   ei       = (const int*)d_in[1];
    const float* emb      = (const float*)d_in[2];
    const float* W        = (const float*)d_in[3];
    const float* att_i    = (const float*)d_in[4];
    const float* att_j    = (const float*)d_in[5];
    const float* att_em_i = (const float*)d_in[6];
    const float* att_em_j = (const float*)d_in[7];
    const float* bias     = (const float*)d_in[8];
    const float* gamma    = (const float*)d_in[9];
    const float* beta     = (const float*)d_in[10];
    float* out = (float*)d_out;

    int N = in_sizes[0] / 64;
    int E = in_sizes[1] / 2;

    k_fused<<<GRID, CTA>>>(x, ei, emb, W, att_i, att_j, att_em_i, att_em_j,
                           bias, gamma, beta, out, N, E);
}

// round 11
// speedup vs baseline: 1.0557x; 1.0320x over previous
#include <cuda_runtime.h>
#include <cuda_fp16.h>

#define MAXN 50176
#define MAXE 850176
#define GRID 888              // 148 SMs x 6 blocks: co-resident on B300(148)/GB300(152)
#define GA   444              // A-blocks: count+scan   (bid < GA)
#define GB   (GRID - GA)      // B-blocks: gemm+logits  (bid >= GA)
#define CTA  256
#define NWARP 8

// -------- scratch (device globals; zero at load; each replay self-restores) --------
__device__ __align__(16) __half2 g_xlh[MAXN * 32];  // lin(x) in fp16, 128B/row
__device__ float  g_si[MAXN];
__device__ float  g_sj[MAXN];
__device__ int    g_deg[MAXN];          // reset in P3
__device__ int    g_rowptr[MAXN + 1];
__device__ int    g_rank[MAXE];
__device__ __align__(16) float2 g_epack[MAXE];  // (.x = src bits, .y = weight)
__device__ float  g_bnsum[128];         // reset by block 0 at end
__device__ int    g_bpart[GA];
__device__ unsigned long long g_bar;    // global ticket counter (monotonic)
__device__ unsigned long long g_barA;   // A-group ticket counter (monotonic)

struct ScanS { int vals[128]; int wred[NWARP]; int off; };
union SmemU {
    float2 Wt2[64][32];                 // 16 KB (B-blocks: gemm)
    ScanS  scan;                        // A-blocks: scan
    float  sred[128];                   // P4 BN partials
    float  bnss[128];                   // P5 scale[0:64) shift[64:128)
};

__device__ __forceinline__ void bar_wait(unsigned long long* ctr, int group) {
    __syncthreads();
    if (threadIdx.x == 0) {
        __threadfence();
        unsigned long long t = atomicAdd(ctr, 1ULL);
        unsigned long long target = t - (t % group) + group;
        while (*(volatile unsigned long long*)ctr < target) __nanosleep(64);
    }
    __syncthreads();
}

__device__ __forceinline__ void scat_one(int s, int d, int pos) {
    float a = g_si[d] + g_sj[s];
    a = a >= 0.f ? a : 0.2f * a;
    g_epack[pos] = make_float2(__int_as_float(s), __expf(a));
}

__global__ void __launch_bounds__(CTA, 6) k_fused(
    const float* __restrict__ x, const int* __restrict__ ei,
    const float* __restrict__ emb, const float* __restrict__ W,
    const float* __restrict__ att_i, const float* __restrict__ att_j,
    const float* __restrict__ att_em_i, const float* __restrict__ att_em_j,
    const float* __restrict__ bias, const float* __restrict__ gamma,
    const float* __restrict__ beta, float* __restrict__ out,
    int N, int E)
{
    __shared__ SmemU sm;
    const int tid = threadIdx.x, bid = blockIdx.x;
    const int lane = tid & 31, wid = tid >> 5;
    const int gtid = bid * CTA + tid;
    const int GT = GRID * CTA;
    const int E4 = E >> 2;

    if (bid < GA) {
        // ============ A: count(+rank) -> scan P1 -> scan P2 ============
        {
            const int AT = GA * CTA;
            int at = bid * CTA + tid;
            for (int t = at; t < E4; t += AT) {
                int4 d4 = *(const int4*)&ei[E + 4 * t];
                int4 r4;
                r4.x = atomicAdd(&g_deg[d4.x], 1);
                r4.y = atomicAdd(&g_deg[d4.y], 1);
                r4.z = atomicAdd(&g_deg[d4.z], 1);
                r4.w = atomicAdd(&g_deg[d4.w], 1);
                *(int4*)&g_rank[4 * t] = r4;
            }
            for (int e = 4 * E4 + at; e < E; e += AT)
                g_rank[e] = atomicAdd(&g_deg[ei[E + e]], 1);
        }
        bar_wait(&g_barA, GA);

        const int CH = (N + GA - 1) / GA;        // 113 for N=50000 (<=128 required)
        int beg = bid * CH;
        int cnt = N - beg; if (cnt < 0) cnt = 0; if (cnt > CH) cnt = CH;
        {   // P1: block partial sum of deg
            int v = (tid < cnt) ? g_deg[beg + tid] : 0;
#pragma unroll
            for (int o = 16; o; o >>= 1) v += __shfl_xor_sync(0xffffffffu, v, o);
            if (lane == 0) sm.scan.wred[wid] = v;
            __syncthreads();
            if (tid == 0) {
                int s = 0;
#pragma unroll
                for (int w2 = 0; w2 < NWARP; w2++) s += sm.scan.wred[w2];
                g_bpart[bid] = s;
            }
        }
        bar_wait(&g_barA, GA);
        {   // P2: block prefix + local scan -> rowptr
            int part = 0;
            for (int j = tid; j < bid; j += CTA) part += g_bpart[j];
#pragma unroll
            for (int o = 16; o; o >>= 1) part += __shfl_xor_sync(0xffffffffu, part, o);
            if (lane == 0) sm.scan.wred[wid] = part;
            __syncthreads();
            if (tid == 0) {
                int s = 0;
#pragma unroll
                for (int w2 = 0; w2 < NWARP; w2++) s += sm.scan.wred[w2];
                sm.scan.off = s;
                if (bid == GA - 1) g_rowptr[N] = s + g_bpart[bid];
            }
            if (tid < 128) sm.scan.vals[tid] = 0;
            __syncthreads();
            int myv = 0;
            if (tid < cnt) { myv = g_deg[beg + tid]; sm.scan.vals[tid] = myv; }
            __syncthreads();
#pragma unroll
            for (int d = 1; d < 128; d <<= 1) {
                int add = (tid < 128 && tid >= d) ? sm.scan.vals[tid - d] : 0;
                __syncthreads();
                if (tid < 128) sm.scan.vals[tid] += add;
                __syncthreads();
            }
            if (tid < cnt)
                g_rowptr[beg + tid] = sm.scan.off + sm.scan.vals[tid] - myv;
        }
    } else {
        // ============ B: gemm + per-node logits (runs concurrently) ============
        for (int s = tid; s < 2048; s += CTA) {
            int k = s >> 5, l = s & 31;
            sm.Wt2[k][l] = make_float2(W[(2 * l) * 64 + k], W[(2 * l + 1) * 64 + k]);
        }
        __syncthreads();
        int c0 = 2 * lane;
        float ai0 = att_i[c0],    ai1 = att_i[c0 + 1];
        float aj0 = att_j[c0],    aj1 = att_j[c0 + 1];
        float e0i = att_em_i[c0], e1i = att_em_i[c0 + 1];
        float e0j = att_em_j[c0], e1j = att_em_j[c0 + 1];
        for (int r = (bid - GA) * NWARP + wid; r < N; r += GB * NWARP) {
            float xv0 = x[r * 64 + lane];
            float xv1 = x[r * 64 + 32 + lane];
            float a0 = 0.f, a1 = 0.f;
#pragma unroll
            for (int k = 0; k < 32; k++) {
                float xk = __shfl_sync(0xffffffffu, xv0, k);
                float2 w = sm.Wt2[k][lane];
                a0 = fmaf(xk, w.x, a0);
                a1 = fmaf(xk, w.y, a1);
            }
#pragma unroll
            for (int k = 0; k < 32; k++) {
                float xk = __shfl_sync(0xffffffffu, xv1, k);
                float2 w = sm.Wt2[32 + k][lane];
                a0 = fmaf(xk, w.x, a0);
                a1 = fmaf(xk, w.y, a1);
            }
            g_xlh[r * 32 + lane] = __floats2half2_rn(a0, a1);   // fp16 storage

            float2 em = *(const float2*)&emb[r * 64 + c0];
            float si = a0 * ai0 + a1 * ai1 + em.x * e0i + em.y * e1i;
            float sj = a0 * aj0 + a1 * aj1 + em.x * e0j + em.y * e1j;
#pragma unroll
            for (int o = 16; o; o >>= 1) {
                si += __shfl_xor_sync(0xffffffffu, si, o);
                sj += __shfl_xor_sync(0xffffffffu, sj, o);
            }
            if (lane == 0) { g_si[r] = si; g_sj[r] = sj; }
        }
    }
    bar_wait(&g_bar, GRID);          // rowptr, rank, xlh, si, sj all ready

    // ================= P3: edge scatter (no atomics) + deg reset ===========
    for (int t = gtid; t < E4; t += GT) {
        int4 s4 = *(const int4*)&ei[4 * t];
        int4 d4 = *(const int4*)&ei[E + 4 * t];
        int4 r4 = *(const int4*)&g_rank[4 * t];
        scat_one(s4.x, d4.x, g_rowptr[d4.x] + r4.x);
        scat_one(s4.y, d4.y, g_rowptr[d4.y] + r4.y);
        scat_one(s4.z, d4.z, g_rowptr[d4.z] + r4.z);
        scat_one(s4.w, d4.w, g_rowptr[d4.w] + r4.w);
    }
    for (int e = 4 * E4 + gtid; e < E; e += GT) {
        int s = ei[e], d = ei[E + e];
        scat_one(s, d, g_rowptr[d] + g_rank[e]);
    }
    for (int i = gtid; i < N; i += GT) g_deg[i] = 0;    // restore for next replay
    bar_wait(&g_bar, GRID);

    // ===== P4: weighted gather (fp16 rows, self-loop analytic) + BN stats =====
    if (tid < 128) sm.sred[tid] = 0.f;
    __syncthreads();
    {
        int c0 = 2 * lane;
        float2 b2 = *(const float2*)&bias[c0];
        float p0 = 0.f, p1 = 0.f, q0 = 0.f, q1 = 0.f;

        for (int i = bid * NWARP + wid; i < N; i += GRID * NWARP) {
            int kb = g_rowptr[i], ke = g_rowptr[i + 1];
            float as = g_si[i] + g_sj[i];            // self loop, analytic
            as = as >= 0.f ? as : 0.2f * as;
            float ws = __expf(as);
            float2 vs = __half22float2(g_xlh[i * 32 + lane]);
            float ssum = ws;
            float ax = ws * vs.x, ay = ws * vs.y;

            int k = kb;
            if ((k & 1) && k < ke) {                 // peel to 16B alignment
                float2 e = g_epack[k];
                int s = __float_as_int(e.x);
                float2 v = __half22float2(g_xlh[s * 32 + lane]);
                ssum += e.y;
                ax = fmaf(e.y, v.x, ax);
                ay = fmaf(e.y, v.y, ay);
                ++k;
            }
            for (; k + 4 <= ke; k += 4) {            // 2x float4 = 4 packed edges
                float4 ea = *(const float4*)&g_epack[k];
                float4 eb = *(const float4*)&g_epack[k + 2];
                int s0 = __float_as_int(ea.x), s1 = __float_as_int(ea.z);
                int s2 = __float_as_int(eb.x), s3 = __float_as_int(eb.z);
                float2 v0 = __half22float2(g_xlh[s0 * 32 + lane]);
                float2 v1 = __half22float2(g_xlh[s1 * 32 + lane]);
                float2 v2 = __half22float2(g_xlh[s2 * 32 + lane]);
                float2 v3 = __half22float2(g_xlh[s3 * 32 + lane]);
                ssum += (ea.y + ea.w) + (eb.y + eb.w);
                ax = fmaf(ea.y, v0.x, ax); ay = fmaf(ea.y, v0.y, ay);
                ax = fmaf(ea.w, v1.x, ax); ay = fmaf(ea.w, v1.y, ay);
                ax = fmaf(eb.y, v2.x, ax); ay = fmaf(eb.y, v2.y, ay);
                ax = fmaf(eb.w, v3.x, ax); ay = fmaf(eb.w, v3.y, ay);
            }
            for (; k < ke; ++k) {
                float2 e = g_epack[k];
                int s = __float_as_int(e.x);
                float2 v = __half22float2(g_xlh[s * 32 + lane]);
                ssum += e.y;
                ax = fmaf(e.y, v.x, ax);
                ay = fmaf(e.y, v.y, ay);
            }
            float inv = 1.f / (ssum + 1e-16f);
            float ox = fmaf(ax, inv, b2.x);
            float oy = fmaf(ay, inv, b2.y);
            *(float2*)&out[i * 64 + c0] = make_float2(ox, oy);
            p0 += ox; q0 = fmaf(ox, ox, q0);
            p1 += oy; q1 = fmaf(oy, oy, q1);
        }
        atomicAdd(&sm.sred[c0],          p0);
        atomicAdd(&sm.sred[c0 + 1],      p1);
        atomicAdd(&sm.sred[64 + c0],     q0);
        atomicAdd(&sm.sred[64 + c0 + 1], q1);
    }
    __syncthreads();
    if (tid < 128) atomicAdd(&g_bnsum[tid], sm.sred[tid]);
    bar_wait(&g_bar, GRID);

    // ================= P5: BN apply + ReLU =================================
    if (tid < 64) {
        double mu  = (double)g_bnsum[tid] / (double)N;
        double var = (double)g_bnsum[64 + tid] / (double)N - mu * mu;
        float sc = (float)rsqrt(var + 1e-5) * gamma[tid];
        sm.bnss[tid]      = sc;
        sm.bnss[64 + tid] = fmaf(-(float)mu, sc, beta[tid]);
    }
    __syncthreads();
    {
        int NV = N * 16;                             // float4 elements
        for (int v = gtid; v < NV; v += GT) {
            float4 o4 = *(float4*)(out + v * 4);
            int c0 = (v & 15) * 4;
            o4.x = fmaxf(fmaf(o4.x, sm.bnss[c0],     sm.bnss[64 + c0]),     0.f);
            o4.y = fmaxf(fmaf(o4.y, sm.bnss[c0 + 1], sm.bnss[64 + c0 + 1]), 0.f);
            o4.z = fmaxf(fmaf(o4.z, sm.bnss[c0 + 2], sm.bnss[64 + c0 + 2]), 0.f);
            o4.w = fmaxf(fmaf(o4.w, sm.bnss[c0 + 3], sm.bnss[64 + c0 + 3]), 0.f);
            *(float4*)(out + v * 4) = o4;
        }
    }

    // final barrier: arrive-all; block 0 waits then resets g_bnsum
    __syncthreads();
    if (tid == 0) {
        __threadfence();
        unsigned long long t = atomicAdd(&g_bar, 1ULL);
        if (bid == 0) {
            unsigned long long target = t - (t % GRID) + GRID;
            while (*(volatile unsigned long long*)&g_bar < target) __nanosleep(64);
        }
    }
    __syncthreads();
    if (bid == 0 && tid < 128) g_bnsum[tid] = 0.f;
}

extern "C" void kernel_launch(void* const* d_in, const int* in_sizes, int n_in,
                              void* d_out, int out_size) {
    const float* x        = (const float*)d_in[0];
    const int*   ei       = (const int*)d_in[1];
    const float* emb      = (const float*)d_in[2];
    const float* W        = (const float*)d_in[3];
    const float* att_i    = (const float*)d_in[4];
    const float* att_j    = (const float*)d_in[5];
    const float* att_em_i = (const float*)d_in[6];
    const float* att_em_j = (const float*)d_in[7];
    const float* bias     = (const float*)d_in[8];
    const float* gamma    = (const float*)d_in[9];
    const float* beta     = (const float*)d_in[10];
    float* out = (float*)d_out;

    int N = in_sizes[0] / 64;
    int E = in_sizes[1] / 2;

    k_fused<<<GRID, CTA>>>(x, ei, emb, W, att_i, att_j, att_em_i, att_em_j,
                           bias, gamma, beta, out, N, E);
}

// round 12
// speedup vs baseline: 1.0569x; 1.0011x over previous
#include <cuda_runtime.h>
#include <cuda_fp16.h>

#define MAXN 50176
#define MAXE 850176
#define GRID 888              // 148 SMs x 6 blocks: co-resident on B300(148)/GB300(152)
#define GA   444              // A-blocks: count+scan   (bid < GA)
#define GB   (GRID - GA)      // B-blocks: gemm+logits  (bid >= GA)
#define CTA  256
#define NWARP 8
#define CHN  ((MAXN + GRID - 1) / GRID)   // 57 nodes per block (compile-time bound)

// -------- scratch (device globals; zero at load; each replay self-restores) --------
__device__ __align__(16) __half2 g_xlh[MAXN * 32];  // lin(x) in fp16, 128B/row
__device__ float  g_si[MAXN];
__device__ float  g_sj[MAXN];
__device__ int    g_deg[MAXN];          // reset in P3
__device__ int    g_rowptr[MAXN + 1];
__device__ int    g_rank[MAXE];
__device__ __align__(16) float2 g_epack[MAXE];  // (.x = src bits, .y = weight)
__device__ float  g_bnsum[128];         // reset by block 0 at end
__device__ int    g_bpart[GA];
__device__ unsigned long long g_bar;    // global ticket counter (monotonic)
__device__ unsigned long long g_barA;   // A-group ticket counter (monotonic)

struct ScanS { int vals[128]; int wred[NWARP]; int off; };
union SmemU {
    float2 Wt2[64][32];                 // 16 KB (B-blocks: gemm)
    ScanS  scan;                        // A-blocks: scan
    float  bnss[128];                   // P5 scale[0:64) shift[64:128)
};

__device__ __forceinline__ void bar_wait(unsigned long long* ctr, int group) {
    __syncthreads();
    if (threadIdx.x == 0) {
        __threadfence();
        unsigned long long t = atomicAdd(ctr, 1ULL);
        unsigned long long target = t - (t % group) + group;
        while (*(volatile unsigned long long*)ctr < target) __nanosleep(64);
    }
    __syncthreads();
}

__device__ __forceinline__ void scat_one(int s, int d, int pos) {
    float a = g_si[d] + g_sj[s];
    a = a >= 0.f ? a : 0.2f * a;
    g_epack[pos] = make_float2(__int_as_float(s), __expf(a));
}

__global__ void __launch_bounds__(CTA, 6) k_fused(
    const float* __restrict__ x, const int* __restrict__ ei,
    const float* __restrict__ emb, const float* __restrict__ W,
    const float* __restrict__ att_i, const float* __restrict__ att_j,
    const float* __restrict__ att_em_i, const float* __restrict__ att_em_j,
    const float* __restrict__ bias, const float* __restrict__ gamma,
    const float* __restrict__ beta, float* __restrict__ out,
    int N, int E)
{
    __shared__ SmemU sm;                               // 16 KB
    __shared__ __align__(16) float sout[CHN * 64];     // 14.25 KB pre-BN staging
    __shared__ float sred[128];                        // BN partials
    const int tid = threadIdx.x, bid = blockIdx.x;
    const int lane = tid & 31, wid = tid >> 5;
    const int gtid = bid * CTA + tid;
    const int GT = GRID * CTA;
    const int E4 = E >> 2;

    if (bid < GA) {
        // ============ A: count(+rank) -> scan P1 -> scan P2 ============
        {
            const int AT = GA * CTA;
            int at = bid * CTA + tid;
            for (int t = at; t < E4; t += AT) {
                int4 d4 = *(const int4*)&ei[E + 4 * t];
                int4 r4;
                r4.x = atomicAdd(&g_deg[d4.x], 1);
                r4.y = atomicAdd(&g_deg[d4.y], 1);
                r4.z = atomicAdd(&g_deg[d4.z], 1);
                r4.w = atomicAdd(&g_deg[d4.w], 1);
                *(int4*)&g_rank[4 * t] = r4;
            }
            for (int e = 4 * E4 + at; e < E; e += AT)
                g_rank[e] = atomicAdd(&g_deg[ei[E + e]], 1);
        }
        bar_wait(&g_barA, GA);

        const int CHA = (N + GA - 1) / GA;        // 113 for N=50000 (<=128 required)
        int abeg = bid * CHA;
        int acnt = N - abeg; if (acnt < 0) acnt = 0; if (acnt > CHA) acnt = CHA;
        {   // P1: block partial sum of deg
            int v = (tid < acnt) ? g_deg[abeg + tid] : 0;
#pragma unroll
            for (int o = 16; o; o >>= 1) v += __shfl_xor_sync(0xffffffffu, v, o);
            if (lane == 0) sm.scan.wred[wid] = v;
            __syncthreads();
            if (tid == 0) {
                int s = 0;
#pragma unroll
                for (int w2 = 0; w2 < NWARP; w2++) s += sm.scan.wred[w2];
                g_bpart[bid] = s;
            }
        }
        bar_wait(&g_barA, GA);
        {   // P2: block prefix + local scan -> rowptr
            int part = 0;
            for (int j = tid; j < bid; j += CTA) part += g_bpart[j];
#pragma unroll
            for (int o = 16; o; o >>= 1) part += __shfl_xor_sync(0xffffffffu, part, o);
            if (lane == 0) sm.scan.wred[wid] = part;
            __syncthreads();
            if (tid == 0) {
                int s = 0;
#pragma unroll
                for (int w2 = 0; w2 < NWARP; w2++) s += sm.scan.wred[w2];
                sm.scan.off = s;
                if (bid == GA - 1) g_rowptr[N] = s + g_bpart[bid];
            }
            if (tid < 128) sm.scan.vals[tid] = 0;
            __syncthreads();
            int myv = 0;
            if (tid < acnt) { myv = g_deg[abeg + tid]; sm.scan.vals[tid] = myv; }
            __syncthreads();
#pragma unroll
            for (int d = 1; d < 128; d <<= 1) {
                int add = (tid < 128 && tid >= d) ? sm.scan.vals[tid - d] : 0;
                __syncthreads();
                if (tid < 128) sm.scan.vals[tid] += add;
                __syncthreads();
            }
            if (tid < acnt)
                g_rowptr[abeg + tid] = sm.scan.off + sm.scan.vals[tid] - myv;
        }
    } else {
        // ============ B: gemm + per-node logits (runs concurrently) ============
        for (int s = tid; s < 2048; s += CTA) {
            int k = s >> 5, l = s & 31;
            sm.Wt2[k][l] = make_float2(W[(2 * l) * 64 + k], W[(2 * l + 1) * 64 + k]);
        }
        __syncthreads();
        int c0 = 2 * lane;
        float ai0 = att_i[c0],    ai1 = att_i[c0 + 1];
        float aj0 = att_j[c0],    aj1 = att_j[c0 + 1];
        float e0i = att_em_i[c0], e1i = att_em_i[c0 + 1];
        float e0j = att_em_j[c0], e1j = att_em_j[c0 + 1];
        for (int r = (bid - GA) * NWARP + wid; r < N; r += GB * NWARP) {
            float xv0 = x[r * 64 + lane];
            float xv1 = x[r * 64 + 32 + lane];
            float a0 = 0.f, a1 = 0.f;
#pragma unroll
            for (int k = 0; k < 32; k++) {
                float xk = __shfl_sync(0xffffffffu, xv0, k);
                float2 w = sm.Wt2[k][lane];
                a0 = fmaf(xk, w.x, a0);
                a1 = fmaf(xk, w.y, a1);
            }
#pragma unroll
            for (int k = 0; k < 32; k++) {
                float xk = __shfl_sync(0xffffffffu, xv1, k);
                float2 w = sm.Wt2[32 + k][lane];
                a0 = fmaf(xk, w.x, a0);
                a1 = fmaf(xk, w.y, a1);
            }
            g_xlh[r * 32 + lane] = __floats2half2_rn(a0, a1);   // fp16 storage

            float2 em = *(const float2*)&emb[r * 64 + c0];
            float si = a0 * ai0 + a1 * ai1 + em.x * e0i + em.y * e1i;
            float sj = a0 * aj0 + a1 * aj1 + em.x * e0j + em.y * e1j;
#pragma unroll
            for (int o = 16; o; o >>= 1) {
                si += __shfl_xor_sync(0xffffffffu, si, o);
                sj += __shfl_xor_sync(0xffffffffu, sj, o);
            }
            if (lane == 0) { g_si[r] = si; g_sj[r] = sj; }
        }
    }
    bar_wait(&g_bar, GRID);          // rowptr, rank, xlh, si, sj all ready

    // ================= P3: edge scatter (no atomics) + deg reset ===========
    for (int t = gtid; t < E4; t += GT) {
        int4 s4 = *(const int4*)&ei[4 * t];
        int4 d4 = *(const int4*)&ei[E + 4 * t];
        int4 r4 = *(const int4*)&g_rank[4 * t];
        scat_one(s4.x, d4.x, g_rowptr[d4.x] + r4.x);
        scat_one(s4.y, d4.y, g_rowptr[d4.y] + r4.y);
        scat_one(s4.z, d4.z, g_rowptr[d4.z] + r4.z);
        scat_one(s4.w, d4.w, g_rowptr[d4.w] + r4.w);
    }
    for (int e = 4 * E4 + gtid; e < E; e += GT) {
        int s = ei[e], d = ei[E + e];
        scat_one(s, d, g_rowptr[d] + g_rank[e]);
    }
    for (int i = gtid; i < N; i += GT) g_deg[i] = 0;    // restore for next replay
    bar_wait(&g_bar, GRID);

    // ===== P4: weighted gather -> SMEM staging (block-contiguous nodes) + BN stats =====
    if (tid < 128) sred[tid] = 0.f;
    __syncthreads();
    const int CH = (N + GRID - 1) / GRID;               // 57 (== CHN bound)
    const int nbeg = bid * CH;
    int ncnt = N - nbeg; if (ncnt < 0) ncnt = 0; if (ncnt > CH) ncnt = CH;
    {
        int c0 = 2 * lane;
        float2 b2 = *(const float2*)&bias[c0];
        float p0 = 0.f, p1 = 0.f, q0 = 0.f, q1 = 0.f;

        for (int j = wid; j < ncnt; j += NWARP) {
            int i = nbeg + j;
            int kb = g_rowptr[i], ke = g_rowptr[i + 1];
            float as = g_si[i] + g_sj[i];            // self loop, analytic
            as = as >= 0.f ? as : 0.2f * as;
            float ws = __expf(as);
            float2 vs = __half22float2(g_xlh[i * 32 + lane]);
            float ssum = ws;
            float ax = ws * vs.x, ay = ws * vs.y;

            int k = kb;
            if ((k & 1) && k < ke) {                 // peel to 16B alignment
                float2 e = g_epack[k];
                int s = __float_as_int(e.x);
                float2 v = __half22float2(g_xlh[s * 32 + lane]);
                ssum += e.y;
                ax = fmaf(e.y, v.x, ax);
                ay = fmaf(e.y, v.y, ay);
                ++k;
            }
            for (; k + 4 <= ke; k += 4) {            // 2x float4 = 4 packed edges
                float4 ea = *(const float4*)&g_epack[k];
                float4 eb = *(const float4*)&g_epack[k + 2];
                int s0 = __float_as_int(ea.x), s1 = __float_as_int(ea.z);
                int s2 = __float_as_int(eb.x), s3 = __float_as_int(eb.z);
                float2 v0 = __half22float2(g_xlh[s0 * 32 + lane]);
                float2 v1 = __half22float2(g_xlh[s1 * 32 + lane]);
                float2 v2 = __half22float2(g_xlh[s2 * 32 + lane]);
                float2 v3 = __half22float2(g_xlh[s3 * 32 + lane]);
                ssum += (ea.y + ea.w) + (eb.y + eb.w);
                ax = fmaf(ea.y, v0.x, ax); ay = fmaf(ea.y, v0.y, ay);
                ax = fmaf(ea.w, v1.x, ax); ay = fmaf(ea.w, v1.y, ay);
                ax = fmaf(eb.y, v2.x, ax); ay = fmaf(eb.y, v2.y, ay);
                ax = fmaf(eb.w, v3.x, ax); ay = fmaf(eb.w, v3.y, ay);
            }
            for (; k < ke; ++k) {
                float2 e = g_epack[k];
                int s = __float_as_int(e.x);
                float2 v = __half22float2(g_xlh[s * 32 + lane]);
                ssum += e.y;
                ax = fmaf(e.y, v.x, ax);
                ay = fmaf(e.y, v.y, ay);
            }
            float inv = 1.f / (ssum + 1e-16f);
            float ox = fmaf(ax, inv, b2.x);
            float oy = fmaf(ay, inv, b2.y);
            *(float2*)&sout[j * 64 + c0] = make_float2(ox, oy);   // stage in smem
            p0 += ox; q0 = fmaf(ox, ox, q0);
            p1 += oy; q1 = fmaf(oy, oy, q1);
        }
        atomicAdd(&sred[c0],          p0);
        atomicAdd(&sred[c0 + 1],      p1);
        atomicAdd(&sred[64 + c0],     q0);
        atomicAdd(&sred[64 + c0 + 1], q1);
    }
    __syncthreads();
    if (tid < 128) atomicAdd(&g_bnsum[tid], sred[tid]);
    bar_wait(&g_bar, GRID);

    // ========= P5: BN apply + ReLU from SMEM staging; out written ONCE =========
    if (tid < 64) {
        double mu  = (double)g_bnsum[tid] / (double)N;
        double var = (double)g_bnsum[64 + tid] / (double)N - mu * mu;
        float sc = (float)rsqrt(var + 1e-5) * gamma[tid];
        sm.bnss[tid]      = sc;
        sm.bnss[64 + tid] = fmaf(-(float)mu, sc, beta[tid]);
    }
    __syncthreads();
    {
        int tot = ncnt * 16;                         // float4 elements in this block
        float* obase = out + (size_t)nbeg * 64;
        for (int v = tid; v < tot; v += CTA) {
            float4 o4 = *(const float4*)&sout[v * 4];
            int c0 = (v & 15) * 4;
            o4.x = fmaxf(fmaf(o4.x, sm.bnss[c0],     sm.bnss[64 + c0]),     0.f);
            o4.y = fmaxf(fmaf(o4.y, sm.bnss[c0 + 1], sm.bnss[64 + c0 + 1]), 0.f);
            o4.z = fmaxf(fmaf(o4.z, sm.bnss[c0 + 2], sm.bnss[64 + c0 + 2]), 0.f);
            o4.w = fmaxf(fmaf(o4.w, sm.bnss[c0 + 3], sm.bnss[64 + c0 + 3]), 0.f);
            *(float4*)(obase + v * 4) = o4;
        }
    }

    // final barrier: arrive-all; block 0 waits then resets g_bnsum
    __syncthreads();
    if (tid == 0) {
        __threadfence();
        unsigned long long t = atomicAdd(&g_bar, 1ULL);
        if (bid == 0) {
            unsigned long long target = t - (t % GRID) + GRID;
            while (*(volatile unsigned long long*)&g_bar < target) __nanosleep(64);
        }
    }
    __syncthreads();
    if (bid == 0 && tid < 128) g_bnsum[tid] = 0.f;
}

extern "C" void kernel_launch(void* const* d_in, const int* in_sizes, int n_in,
                              void* d_out, int out_size) {
    const float* x        = (const float*)d_in[0];
    const int*   ei       = (const int*)d_in[1];
    const float* emb      = (const float*)d_in[2];
    const float* W        = (const float*)d_in[3];
    const float* att_i    = (const float*)d_in[4];
    const float* att_j    = (const float*)d_in[5];
    const float* att_em_i = (const float*)d_in[6];
    const float* att_em_j = (const float*)d_in[7];
    const float* bias     = (const float*)d_in[8];
    const float* gamma    = (const float*)d_in[9];
    const float* beta     = (const float*)d_in[10];
    float* out = (float*)d_out;

    int N = in_sizes[0] / 64;
    int E = in_sizes[1] / 2;

    k_fused<<<GRID, CTA>>>(x, ei, emb, W, att_i, att_j, att_em_i, att_em_j,
                           bias, gamma, beta, out, N, E);
}

// round 13
// speedup vs baseline: 1.1530x; 1.0910x over previous
#include <cuda_runtime.h>
#include <cuda_fp16.h>

#define MAXN 50176
#define MAXE 850176
#define GRID 444              // 148 SMs x 3 blocks (152-SM GB300: 444 < 456) — co-resident
#define GA   222              // A-blocks: count+scan   (bid < GA)
#define GB   (GRID - GA)      // B-blocks: gemm+logits  (bid >= GA)
#define CTA  512
#define NWARP 16
#define NBAR 3                // global barriers per replay (for parity epoch)

// -------- scratch (device globals; zero at load; each replay self-restores) --------
__device__ __align__(16) __half2 g_xlh[MAXN * 32];  // lin(x) in fp16, 128B/row
__device__ float  g_si[MAXN];
__device__ float  g_sj[MAXN];
__device__ int    g_deg[MAXN];          // reset in P3
__device__ int    g_rowptr[MAXN + 1];
__device__ int    g_rank[MAXE];
__device__ __align__(16) float2 g_epack[MAXE];  // (.x = src bits, .y = weight)
__device__ float  g_bnsum[256];         // parity double-buffer [p*128 .. p*128+128)
__device__ int    g_bpart[GA];
__device__ unsigned long long g_bar;    // global ticket counter (monotonic)
__device__ unsigned long long g_barA;   // A-group ticket counter (monotonic)

struct ScanS { int vals[CTA]; int wred[NWARP]; int off; };
union SmemU {
    float2 Wt2[64][32];                 // 16 KB (B-blocks: gemm)
    ScanS  scan;                        // A-blocks: scan (2 KB region)
    float  bnss[128];                   // P5 scale[0:64) shift[64:128)
};

__device__ __forceinline__ void bar_wait(unsigned long long* ctr, int group) {
    __syncthreads();
    if (threadIdx.x == 0) {
        __threadfence();
        unsigned long long t = atomicAdd(ctr, 1ULL);
        unsigned long long target = t - (t % group) + group;
        while (*(volatile unsigned long long*)ctr < target) __nanosleep(64);
    }
    __syncthreads();
}

__device__ __forceinline__ void scat_one(int s, int d, int pos) {
    float a = g_si[d] + g_sj[s];
    a = a >= 0.f ? a : 0.2f * a;
    g_epack[pos] = make_float2(__int_as_float(s), __expf(a));
}

__global__ void __launch_bounds__(CTA, 3) k_fused(
    const float* __restrict__ x, const int* __restrict__ ei,
    const float* __restrict__ emb, const float* __restrict__ W,
    const float* __restrict__ att_i, const float* __restrict__ att_j,
    const float* __restrict__ att_em_i, const float* __restrict__ att_em_j,
    const float* __restrict__ bias, const float* __restrict__ gamma,
    const float* __restrict__ beta, float* __restrict__ out,
    int N, int E)
{
    __shared__ SmemU sm;                 // 16 KB
    __shared__ float sred[128];          // BN partials
    __shared__ int s_parity;
    const int tid = threadIdx.x, bid = blockIdx.x;
    const int lane = tid & 31, wid = tid >> 5;
    const int gtid = bid * CTA + tid;
    const int GT = GRID * CTA;
    const int E4 = E >> 2;

    // ---- epoch parity from monotonic counter (read before any increment overflow:
    //      <GRID increments can precede a slow block's start, floor stays exact) ----
    if (tid == 0) {
        unsigned long long b = *(volatile unsigned long long*)&g_bar;
        s_parity = (int)((b / (unsigned long long)(NBAR * GRID)) & 1ULL);
    }
    __syncthreads();
    const int parity = s_parity;
    if (bid == 0 && tid < 128) g_bnsum[(parity ^ 1) * 128 + tid] = 0.f; // prep next replay

    if (bid < GA) {
        // ============ A: count(+rank) -> scan P1 -> scan P2 ============
        {
            const int AT = GA * CTA;
            int at = bid * CTA + tid;
            for (int t = at; t < E4; t += AT) {
                int4 d4 = *(const int4*)&ei[E + 4 * t];
                int4 r4;
                r4.x = atomicAdd(&g_deg[d4.x], 1);
                r4.y = atomicAdd(&g_deg[d4.y], 1);
                r4.z = atomicAdd(&g_deg[d4.z], 1);
                r4.w = atomicAdd(&g_deg[d4.w], 1);
                *(int4*)&g_rank[4 * t] = r4;
            }
            for (int e = 4 * E4 + at; e < E; e += AT)
                g_rank[e] = atomicAdd(&g_deg[ei[E + e]], 1);
        }
        bar_wait(&g_barA, GA);

        const int CHA = (N + GA - 1) / GA;        // 226 for N=50000 (<=CTA required)
        int abeg = bid * CHA;
        int acnt = N - abeg; if (acnt < 0) acnt = 0; if (acnt > CHA) acnt = CHA;
        {   // P1: block partial sum of deg
            int v = (tid < acnt) ? g_deg[abeg + tid] : 0;
#pragma unroll
            for (int o = 16; o; o >>= 1) v += __shfl_xor_sync(0xffffffffu, v, o);
            if (lane == 0) sm.scan.wred[wid] = v;
            __syncthreads();
            if (tid == 0) {
                int s = 0;
#pragma unroll
                for (int w2 = 0; w2 < NWARP; w2++) s += sm.scan.wred[w2];
                g_bpart[bid] = s;
            }
        }
        bar_wait(&g_barA, GA);
        {   // P2: block prefix + local scan -> rowptr
            int part = 0;
            for (int j = tid; j < bid; j += CTA) part += g_bpart[j];
#pragma unroll
            for (int o = 16; o; o >>= 1) part += __shfl_xor_sync(0xffffffffu, part, o);
            if (lane == 0) sm.scan.wred[wid] = part;
            __syncthreads();
            if (tid == 0) {
                int s = 0;
#pragma unroll
                for (int w2 = 0; w2 < NWARP; w2++) s += sm.scan.wred[w2];
                sm.scan.off = s;
                if (bid == GA - 1) g_rowptr[N] = s + g_bpart[bid];
            }
            sm.scan.vals[tid] = 0;
            __syncthreads();
            int myv = 0;
            if (tid < acnt) { myv = g_deg[abeg + tid]; sm.scan.vals[tid] = myv; }
            __syncthreads();
#pragma unroll
            for (int d = 1; d < CTA; d <<= 1) {
                int add = (tid >= d) ? sm.scan.vals[tid - d] : 0;
                __syncthreads();
                sm.scan.vals[tid] += add;
                __syncthreads();
            }
            if (tid < acnt)
                g_rowptr[abeg + tid] = sm.scan.off + sm.scan.vals[tid] - myv;
        }
    } else {
        // ============ B: gemm + per-node logits (runs concurrently) ============
        for (int s = tid; s < 2048; s += CTA) {
            int k = s >> 5, l = s & 31;
            sm.Wt2[k][l] = make_float2(W[(2 * l) * 64 + k], W[(2 * l + 1) * 64 + k]);
        }
        __syncthreads();
        int c0 = 2 * lane;
        float ai0 = att_i[c0],    ai1 = att_i[c0 + 1];
        float aj0 = att_j[c0],    aj1 = att_j[c0 + 1];
        float e0i = att_em_i[c0], e1i = att_em_i[c0 + 1];
        float e0j = att_em_j[c0], e1j = att_em_j[c0 + 1];
        for (int r = (bid - GA) * NWARP + wid; r < N; r += GB * NWARP) {
            float xv0 = x[r * 64 + lane];
            float xv1 = x[r * 64 + 32 + lane];
            float a0 = 0.f, a1 = 0.f;
#pragma unroll
            for (int k = 0; k < 32; k++) {
                float xk = __shfl_sync(0xffffffffu, xv0, k);
                float2 w = sm.Wt2[k][lane];
                a0 = fmaf(xk, w.x, a0);
                a1 = fmaf(xk, w.y, a1);
            }
#pragma unroll
            for (int k = 0; k < 32; k++) {
                float xk = __shfl_sync(0xffffffffu, xv1, k);
                float2 w = sm.Wt2[32 + k][lane];
                a0 = fmaf(xk, w.x, a0);
                a1 = fmaf(xk, w.y, a1);
            }
            g_xlh[r * 32 + lane] = __floats2half2_rn(a0, a1);   // fp16 storage

            float2 em = *(const float2*)&emb[r * 64 + c0];
            float si = a0 * ai0 + a1 * ai1 + em.x * e0i + em.y * e1i;
            float sj = a0 * aj0 + a1 * aj1 + em.x * e0j + em.y * e1j;
#pragma unroll
            for (int o = 16; o; o >>= 1) {
                si += __shfl_xor_sync(0xffffffffu, si, o);
                sj += __shfl_xor_sync(0xffffffffu, sj, o);
            }
            if (lane == 0) { g_si[r] = si; g_sj[r] = sj; }
        }
    }
    bar_wait(&g_bar, GRID);          // rowptr, rank, xlh, si, sj all ready

    // ================= P3: edge scatter (no atomics) + deg reset ===========
    for (int t = gtid; t < E4; t += GT) {
        int4 s4 = *(const int4*)&ei[4 * t];
        int4 d4 = *(const int4*)&ei[E + 4 * t];
        int4 r4 = *(const int4*)&g_rank[4 * t];
        scat_one(s4.x, d4.x, g_rowptr[d4.x] + r4.x);
        scat_one(s4.y, d4.y, g_rowptr[d4.y] + r4.y);
        scat_one(s4.z, d4.z, g_rowptr[d4.z] + r4.z);
        scat_one(s4.w, d4.w, g_rowptr[d4.w] + r4.w);
    }
    for (int e = 4 * E4 + gtid; e < E; e += GT) {
        int s = ei[e], d = ei[E + e];
        scat_one(s, d, g_rowptr[d] + g_rank[e]);
    }
    for (int i = gtid; i < N; i += GT) g_deg[i] = 0;    // restore for next replay
    bar_wait(&g_bar, GRID);

    // ===== P4: weighted gather (fp16 rows, self-loop analytic) + BN stats =====
    if (tid < 128) sred[tid] = 0.f;
    __syncthreads();
    {
        int c0 = 2 * lane;
        float2 b2 = *(const float2*)&bias[c0];
        float p0 = 0.f, p1 = 0.f, q0 = 0.f, q1 = 0.f;

        for (int i = bid * NWARP + wid; i < N; i += GRID * NWARP) {
            int kb = g_rowptr[i], ke = g_rowptr[i + 1];
            float as = g_si[i] + g_sj[i];            // self loop, analytic
            as = as >= 0.f ? as : 0.2f * as;
            float ws = __expf(as);
            float2 vs = __half22float2(g_xlh[i * 32 + lane]);
            float ssum = ws;
            float ax = ws * vs.x, ay = ws * vs.y;

            int k = kb;
            if ((k & 1) && k < ke) {                 // peel to 16B alignment
                float2 e = g_epack[k];
                int s = __float_as_int(e.x);
                float2 v = __half22float2(g_xlh[s * 32 + lane]);
                ssum += e.y;
                ax = fmaf(e.y, v.x, ax);
                ay = fmaf(e.y, v.y, ay);
                ++k;
            }
            for (; k + 4 <= ke; k += 4) {            // 2x float4 = 4 packed edges
                float4 ea = *(const float4*)&g_epack[k];
                float4 eb = *(const float4*)&g_epack[k + 2];
                int s0 = __float_as_int(ea.x), s1 = __float_as_int(ea.z);
                int s2 = __float_as_int(eb.x), s3 = __float_as_int(eb.z);
                float2 v0 = __half22float2(g_xlh[s0 * 32 + lane]);
                float2 v1 = __half22float2(g_xlh[s1 * 32 + lane]);
                float2 v2 = __half22float2(g_xlh[s2 * 32 + lane]);
                float2 v3 = __half22float2(g_xlh[s3 * 32 + lane]);
                ssum += (ea.y + ea.w) + (eb.y + eb.w);
                ax = fmaf(ea.y, v0.x, ax); ay = fmaf(ea.y, v0.y, ay);
                ax = fmaf(ea.w, v1.x, ax); ay = fmaf(ea.w, v1.y, ay);
                ax = fmaf(eb.y, v2.x, ax); ay = fmaf(eb.y, v2.y, ay);
                ax = fmaf(eb.w, v3.x, ax); ay = fmaf(eb.w, v3.y, ay);
            }
            for (; k < ke; ++k) {
                float2 e = g_epack[k];
                int s = __float_as_int(e.x);
                float2 v = __half22float2(g_xlh[s * 32 + lane]);
                ssum += e.y;
                ax = fmaf(e.y, v.x, ax);
                ay = fmaf(e.y, v.y, ay);
            }
            float inv = 1.f / (ssum + 1e-16f);
            float ox = fmaf(ax, inv, b2.x);
            float oy = fmaf(ay, inv, b2.y);
            *(float2*)&out[i * 64 + c0] = make_float2(ox, oy);
            p0 += ox; q0 = fmaf(ox, ox, q0);
            p1 += oy; q1 = fmaf(oy, oy, q1);
        }
        atomicAdd(&sred[c0],          p0);
        atomicAdd(&sred[c0 + 1],      p1);
        atomicAdd(&sred[64 + c0],     q0);
        atomicAdd(&sred[64 + c0 + 1], q1);
    }
    __syncthreads();
    if (tid < 128) atomicAdd(&g_bnsum[parity * 128 + tid], sred[tid]);
    bar_wait(&g_bar, GRID);

    // ================= P5: BN apply + ReLU (no final barrier needed) ========
    if (tid < 64) {
        double mu  = (double)g_bnsum[parity * 128 + tid] / (double)N;
        double var = (double)g_bnsum[parity * 128 + 64 + tid] / (double)N - mu * mu;
        float sc = (float)rsqrt(var + 1e-5) * gamma[tid];
        sm.bnss[tid]      = sc;
        sm.bnss[64 + tid] = fmaf(-(float)mu, sc, beta[tid]);
    }
    __syncthreads();
    {
        int NV = N * 16;                             // float4 elements
        for (int v = gtid; v < NV; v += GT) {
            float4 o4 = *(float4*)(out + v * 4);
            int c0 = (v & 15) * 4;
            o4.x = fmaxf(fmaf(o4.x, sm.bnss[c0],     sm.bnss[64 + c0]),     0.f);
            o4.y = fmaxf(fmaf(o4.y, sm.bnss[c0 + 1], sm.bnss[64 + c0 + 1]), 0.f);
            o4.z = fmaxf(fmaf(o4.z, sm.bnss[c0 + 2], sm.bnss[64 + c0 + 2]), 0.f);
            o4.w = fmaxf(fmaf(o4.w, sm.bnss[c0 + 3], sm.bnss[64 + c0 + 3]), 0.f);
            *(float4*)(out + v * 4) = o4;
        }
    }
}

extern "C" void kernel_launch(void* const* d_in, const int* in_sizes, int n_in,
                              void* d_out, int out_size) {
    const float* x        = (const float*)d_in[0];
    const int*   ei       = (const int*)d_in[1];
    const float* emb      = (const float*)d_in[2];
    const float* W        = (const float*)d_in[3];
    const float* att_i    = (const float*)d_in[4];
    const float* att_j    = (const float*)d_in[5];
    const float* att_em_i = (const float*)d_in[6];
    const float* att_em_j = (const float*)d_in[7];
    const float* bias     = (const float*)d_in[8];
    const float* gamma    = (const float*)d_in[9];
    const float* beta     = (const float*)d_in[10];
    float* out = (float*)d_out;

    int N = in_sizes[0] / 64;
    int E = in_sizes[1] / 2;

    k_fused<<<GRID, CTA>>>(x, ei, emb, W, att_i, att_j, att_em_i, att_em_j,
                           bias, gamma, beta, out, N, E);
}